// round 17
// baseline (speedup 1.0000x reference)
#include <cuda_runtime.h>
#include <cstdint>
#include <math.h>

// Sampler: temperature 0.8, top-k, top-p 0.9, inverse-CDF multinomial. f32 output.
// Single kernel, one block per row. Moment threshold (post-hoc verified), DOUBLE-
// BUFFERED stream (ping-pong register buffers, loads always in flight), bitonic
// candidate sort, parallel bit-exact epilogue (R16, measured win).

#define NT 1024
#define F4PT 4
#define CHUNK_F4 (NT * F4PT)        // 4096 float4 = 16384 floats / chunk
#define BUF_N 4096
#define MAXEPI 256
#define FEPI 64

typedef unsigned long long u64;
typedef unsigned int u32;

__device__ __forceinline__ u32 flip32(u32 f) {
    return (f & 0x80000000u) ? ~f : (f | 0x80000000u);
}
__device__ __forceinline__ u32 unflip32(u32 g) {
    return (g & 0x80000000u) ? (g & 0x7FFFFFFFu) : ~g;
}

struct Sh {
    int cnt;
    float red1[32];
    float red2[32];
    float mu, sg;
    int   kk, m;
    float x0, d1, d2;
    float x[MAXEPI];
    float e[MAXEPI];
    int   id[MAXEPI];
    float p[FEPI];
};

__device__ __forceinline__ void load_chunk(const float4* __restrict__ rp, int nf4,
                                           int base, int tid, float NEG,
                                           float4 (&v)[F4PT]) {
#pragma unroll
    for (int q = 0; q < F4PT; q++) {
        int f4i = base + q * NT + tid;
        v[q] = (f4i < nf4) ? rp[f4i] : make_float4(NEG, NEG, NEG, NEG);
    }
}

__device__ __forceinline__ void proc_chunk(const float4 (&v)[F4PT], int base,
                                           int tid, float t,
                                           u64* buf, int* cnt) {
#pragma unroll
    for (int q = 0; q < F4PT; q++) {
        const float4 a = v[q];
        const float gm = fmaxf(fmaxf(a.x, a.y), fmaxf(a.z, a.w));
        if (gm >= t) {
            const int f4i = base + q * NT + tid;
            const float vv[4] = {a.x, a.y, a.z, a.w};
#pragma unroll
            for (int e = 0; e < 4; e++) {
                if (vv[e] >= t) {   // OOB pads are -inf -> false
                    int s = atomicAdd(cnt, 1);
                    if (s < BUF_N)
                        buf[s] = ((u64)flip32(__float_as_uint(vv[e])) << 32)
                               | (u32)(0xFFFFFFFFu - (u32)(f4i * 4 + e));
                }
            }
        }
    }
}

__global__ __launch_bounds__(NT)
void Sampler_24446953849417_kernel(const float* __restrict__ logits,
                                   const float* __restrict__ u,
                                   const int* __restrict__ kptr,
                                   float* __restrict__ out, int V)
{
    __shared__ u64 buf[BUF_N];      // 32 KB
    __shared__ Sh sh;               // ~3.6 KB

    const int row = blockIdx.x;
    const int tid = threadIdx.x;
    const int lane = tid & 31;
    const int wid = tid >> 5;

    const float4* __restrict__ rp =
        reinterpret_cast<const float4*>(logits + (size_t)row * (size_t)V);
    const int nf4 = V >> 2;
    const int nchunks = (nf4 + CHUNK_F4 - 1) / CHUNK_F4;
    const float NEG = __int_as_float(0xff800000);

    int k = 50;
    if (kptr) {
        int kv = kptr[0];
        if (kv >= 1 && kv <= 100000) k = kv;
        else {
            float kf = __int_as_float(kv);
            if (kf >= 1.0f && kf <= 100000.0f) k = (int)kf;
        }
    }
    k = max(1, min(k, MAXEPI));

    // ---- stats over an 8192-elem sample (shuffle-only reduction) ----
    {
        float s1 = 0.f, s2 = 0.f;
#pragma unroll
        for (int q = 0; q < 2; q++) {
            int f4i = q * NT + tid;
            if (f4i < nf4) {
                float4 a = rp[f4i];
                s1 += a.x + a.y + a.z + a.w;
                s2 += a.x * a.x + a.y * a.y + a.z * a.z + a.w * a.w;
            }
        }
#pragma unroll
        for (int d = 16; d > 0; d >>= 1) {
            s1 += __shfl_down_sync(0xffffffffu, s1, d);
            s2 += __shfl_down_sync(0xffffffffu, s2, d);
        }
        if (lane == 0) { sh.red1[wid] = s1; sh.red2[wid] = s2; }
        __syncthreads();
        if (wid == 0) {
            float t1 = sh.red1[lane];
            float t2 = sh.red2[lane];
#pragma unroll
            for (int d = 16; d > 0; d >>= 1) {
                t1 += __shfl_down_sync(0xffffffffu, t1, d);
                t2 += __shfl_down_sync(0xffffffffu, t2, d);
            }
            if (lane == 0) {
                float n0 = (float)min(2 * NT * 4, nf4 * 4);
                float mu = t1 / n0;
                float var = t2 / n0 - mu * mu;
                sh.mu = mu;
                sh.sg = sqrtf(fmaxf(var, 0.f));
            }
        }
        __syncthreads();
    }
    const float mu = sh.mu;
    const float sg = sh.sg;

    // ---- double-buffered stream with post-hoc verified threshold ----
    float c = 3.0f;
    float t = mu + c * sg;
    int cnt = 0;
    for (int att = 0; att < 8; att++) {
        if (tid == 0) sh.cnt = 0;
        __syncthreads();

        float4 A[F4PT], B[F4PT];
        load_chunk(rp, nf4, 0, tid, NEG, A);
        int ch = 0;
        while (ch < nchunks) {
            // A holds chunk ch
            if (ch + 1 < nchunks) load_chunk(rp, nf4, (ch + 1) * CHUNK_F4, tid, NEG, B);
            proc_chunk(A, ch * CHUNK_F4, tid, t, buf, &sh.cnt);
            ch++;
            if (ch >= nchunks) break;
            // B holds chunk ch
            if (ch + 1 < nchunks) load_chunk(rp, nf4, (ch + 1) * CHUNK_F4, tid, NEG, A);
            proc_chunk(B, ch * CHUNK_F4, tid, t, buf, &sh.cnt);
            ch++;
        }
        for (int idx = nf4 * 4 + tid; idx < V; idx += NT) {   // scalar tail
            float val = logits[(size_t)row * (size_t)V + idx];
            if (val >= t) {
                int s = atomicAdd(&sh.cnt, 1);
                if (s < BUF_N)
                    buf[s] = ((u64)flip32(__float_as_uint(val)) << 32)
                           | (u32)(0xFFFFFFFFu - (u32)idx);
            }
        }
        __syncthreads();

        cnt = sh.cnt;
        // cnt >= k  =>  {x >= t} provably contains the full top-k (+ ties).
        if ((cnt >= k && cnt <= BUF_N) || att == 7) break;
        c = (cnt < k) ? (c - 0.7f) : (c + 0.6f);
        t = mu + c * sg;
        __syncthreads();
    }
    cnt = min(cnt, BUF_N);

    // ---- bitonic sort candidates desc (value desc, index asc on ties) ----
    int n = 1;
    while (n < cnt) n <<= 1;
    for (int j = cnt + tid; j < n; j += NT) buf[j] = 0ull;
    __syncthreads();
    for (int k2 = 2; k2 <= n; k2 <<= 1) {
        for (int s = k2 >> 1; s > 0; s >>= 1) {
            for (int j = tid; j < n; j += NT) {
                int l = j ^ s;
                if (l > j) {
                    u64 a = buf[j], b = buf[l];
                    bool desc = ((j & k2) == 0);
                    if ((a < b) == desc) { buf[j] = b; buf[l] = a; }
                }
            }
            __syncthreads();
        }
    }

    // ---- unpack (value desc, stable ties == argsort(-x)) ----
    const int L = min(cnt, MAXEPI);
    for (int i = tid; i < L; i += NT) {
        u64 key = buf[i];
        sh.x[i]  = __fdiv_rn(__uint_as_float(unflip32((u32)(key >> 32))), 0.8f);
        sh.id[i] = (int)(0xFFFFFFFFu - (u32)(key & 0xFFFFFFFFu));
    }
    __syncthreads();

    // ---- header: kc, x0, kth, kk ----
    if (tid == 0) {
        if (L < 1) { sh.kk = 0; }
        else {
            int kc = min(k, L);
            sh.x0 = sh.x[0];
            float kth = sh.x[kc - 1];
            int kk = kc;
            while (kk < L && sh.x[kk] >= kth) kk++;
            sh.kk = kk;
        }
    }
    __syncthreads();
    const int kk = sh.kk;
    const float uu = u ? u[row] : 0.5f;

    if (kk >= 1 && kk <= FEPI) {
        // ---- FAST epilogue (bit-exact parallel restructuring; R16 measured win) ----
        const float x0 = sh.x0;
        if (tid < FEPI)
            sh.e[tid] = (tid < kk) ? expf(__fadd_rn(sh.x[tid], -x0)) : 0.f;
        __syncthreads();
        if (tid == 0) {
            float d1 = 0.f;
#pragma unroll
            for (int i = 0; i < FEPI; i++) d1 = __fadd_rn(d1, sh.e[i]);
            sh.d1 = d1;
        }
        __syncthreads();
        if (tid < FEPI)
            sh.p[tid] = (tid < kk) ? __fdiv_rn(sh.e[tid], sh.d1) : 0.f;
        __syncthreads();
        if (tid == 0) {
            float cp = 0.f; int m = 0;
#pragma unroll
            for (int i = 0; i < FEPI; i++) {
                bool act = (i < kk) && (i == 0 || !(cp > 0.9f));
                if (act) { m++; cp = __fadd_rn(cp, sh.p[i]); }
            }
            sh.m = m;
        }
        __syncthreads();
        const int m = sh.m;

        if (tid < FEPI) {
            buf[tid] = (tid < m)
                ? (((u64)(u32)sh.id[tid] << 32) | (u64)__float_as_uint(sh.e[tid]))
                : ((u64)0xFFFFFFFFu << 32);
        }
        __syncthreads();
        for (int k2 = 2; k2 <= FEPI; k2 <<= 1) {
            for (int s = k2 >> 1; s > 0; s >>= 1) {
                if (tid < FEPI) {
                    int j = tid, l = j ^ s;
                    if (l > j) {
                        u64 a = buf[j], b = buf[l];
                        bool asc = ((j & k2) == 0);
                        if ((a > b) == asc) { buf[j] = b; buf[l] = a; }
                    }
                }
                __syncthreads();
            }
        }
        if (tid < FEPI) sh.e[tid] = __uint_as_float((u32)(buf[tid] & 0xFFFFFFFFu));
        __syncthreads();
        if (tid == 0) {
            float d2 = 0.f;
#pragma unroll
            for (int i = 0; i < FEPI; i++) d2 = __fadd_rn(d2, sh.e[i]);
            sh.d2 = d2;
        }
        __syncthreads();
        if (tid < FEPI)
            sh.p[tid] = (tid < m) ? __fdiv_rn(sh.e[tid], sh.d2) : 0.f;
        __syncthreads();
        if (tid == 0) {
            float S = 0.f; int idx = 0;
#pragma unroll
            for (int i = 0; i < FEPI; i++) {
                if (i < m) {
                    S = __fadd_rn(S, sh.p[i]);
                    if (S <= uu) idx++;
                }
            }
            int ans = (idx < m) ? (int)(buf[idx] >> 32) : V;
            out[row] = (float)ans;
        }
    } else {
        // ---- fallback: verbatim serial epilogue (kk==0 or kk>64) ----
        if (tid == 0) {
            int ans = V;
            if (L >= 1) {
                int kc = min(k, L);
                const float x0 = sh.x[0];
                const float kth = sh.x[kc - 1];
                int kk2 = kc;
                while (kk2 < L && sh.x[kk2] >= kth) kk2++;

                float d1 = 0.f;
                for (int i = 0; i < kk2; i++) {
                    float ee = expf(__fadd_rn(sh.x[i], -x0));
                    sh.e[i] = ee;
                    d1 = __fadd_rn(d1, ee);
                }
                float cprev = 0.f;
                int m = 0;
                for (int i = 0; i < kk2; i++) {
                    if (i > 0 && cprev > 0.9f) break;
                    m++;
                    cprev = __fadd_rn(cprev, __fdiv_rn(sh.e[i], d1));
                }
                for (int i = 1; i < m; i++) {
                    int idv = sh.id[i]; float ev = sh.e[i]; int j = i - 1;
                    while (j >= 0 && sh.id[j] > idv) {
                        sh.id[j + 1] = sh.id[j]; sh.e[j + 1] = sh.e[j]; j--;
                    }
                    sh.id[j + 1] = idv; sh.e[j + 1] = ev;
                }
                float d2 = 0.f;
                for (int i = 0; i < m; i++) d2 = __fadd_rn(d2, sh.e[i]);

                float S = 0.f;
                for (int i = 0; i < m; i++) {
                    S = __fadd_rn(S, __fdiv_rn(sh.e[i], d2));
                    if (S > uu) { ans = sh.id[i]; break; }
                }
            }
            out[row] = (float)ans;
        }
    }
}

extern "C" void kernel_launch(void* const* d_in, const int* in_sizes, int n_in,
                              void* d_out, int out_size) {
    int li = 0;
    for (int i = 1; i < n_in; i++)
        if (in_sizes[i] > in_sizes[li]) li = i;

    const int B = out_size;
    const float* logits = (const float*)d_in[li];
    const float* u = nullptr;
    const int* kp = nullptr;
    for (int i = 0; i < n_in; i++) {
        if (i == li) continue;
        if (in_sizes[i] == B) u = (const float*)d_in[i];
        else if (in_sizes[i] == 1) kp = (const int*)d_in[i];
    }
    if (!u) {
        for (int i = 0; i < n_in; i++)
            if (i != li && in_sizes[i] != 1) { u = (const float*)d_in[i]; break; }
    }

    int V = in_sizes[li] / B;
    if (V * B != in_sizes[li]) {
        int Vb = in_sizes[li] / 4 / B;
        if (Vb * B * 4 == in_sizes[li]) V = Vb;
    }

    Sampler_24446953849417_kernel<<<B, NT>>>(logits, u, kp, (float*)d_out, V);
}